// round 16
// baseline (speedup 1.0000x reference)
#include <cuda_runtime.h>
#include <cstdint>
#include <cstddef>

// Problem constants
#define TT   255
#define BB   256
#define KK   784
#define NN   40
#define MM   (TT * BB)          // 65280
#define PLANE (BB * NN)         // 10240 elements per timestep
#define OUT_HALF (TT * PLANE)   // 2,611,200

// Scratch for cur = x @ W^T   (10.44 MB, static device global: allowed)
__device__ float g_cur[(size_t)MM * NN];

// packed f32x2 FMA: d = fma(a, b, d) per lane (IEEE rn, fused)
__device__ __forceinline__ void fma2(unsigned long long& d,
                                     unsigned long long a,
                                     unsigned long long b) {
    asm("fma.rn.f32x2 %0, %1, %2, %3;" : "=l"(d) : "l"(a), "l"(b), "l"(d));
}
// packed f32x2 add (rn)
__device__ __forceinline__ unsigned long long add2(unsigned long long a,
                                                   unsigned long long b) {
    unsigned long long d;
    asm("add.rn.f32x2 %0, %1, %2;" : "=l"(d) : "l"(a), "l"(b));
    return d;
}

// ---------------------------------------------------------------------------
// No-op kernel, launched LAST: with the harness's 2 pre-launches, ncu's
// -s 5 -c 1 capture lands on snn_gemm_kernel ((5-2) mod 3 == 0). Proven R15.
// ---------------------------------------------------------------------------
__global__ void snn_nop_kernel() {}

// ---------------------------------------------------------------------------
// Kernel 1: cur[m][n] = sum_k x[m][k] * W[n][k]
//
// Rounding scheme (bit-identical to all passing rounds):
//   8 chains, chain j = fused-FMA over k ≡ j (mod 8) ascending;
//   combine: ((c0+c4)+(c1+c5)) + ((c2+c6)+(c3+c7))
//   realized by phase-per-thread + butterfly shuffles xor {4,1,2}.
//
// R16 CHANGE (only): A prefetch distance 2 -> 3. a_st[2] double register
// buffer: LDG(c+3) is issued at iter c and consumed (STS) at iter c+2,
// giving ~2 chunk-periods of slack (> loaded DRAM latency), instead of 1
// (which exposed ~300 cyc of stall every chunk -> the measured issue=37%).
// W stays at distance 2 (L2-resident: re-read by all 1020 blocks).
//
// 256 threads = 8 phases x 32 workers (8 row-groups x TM=8, 4 col-groups x
// TN=10). BM=64, BN=40, BK=16, grid = 1020, 2 CTAs/SM.
// ---------------------------------------------------------------------------
#define NCHUNK (KK / 16)    // 49

__global__ __launch_bounds__(256, 2)
void snn_gemm_kernel(const float* __restrict__ x, const float* __restrict__ W) {
    __shared__ float  As[2][16][68];
    __shared__ float2 Ws2[2][16][42];

    const int tid   = threadIdx.x;
    const int phase = tid & 7;          // chain index 0..7
    const int ww    = tid >> 3;         // worker 0..31
    const int wrow  = ww & 7;           // 8 row groups * TM=8 -> BM=64
    const int wcol  = ww >> 3;          // 4 col groups * TN=10 -> BN=40
    const int mbase = blockIdx.x * 64;

    // Staging-load geometry
    const int arow = tid >> 2;          // 0..63
    const int aq   = tid & 3;           // 0..3 (float4 within 16-k chunk)
    const float* __restrict__ aptr = x + (size_t)(mbase + arow) * KK + aq * 4;
    const int  wn      = tid >> 2;      // n index for W staging
    const int  wq      = tid & 3;
    const bool wactive = (tid < 160);   // 40 n * 4 quads
    const float* __restrict__ wptr = W + (size_t)wn * KK + wq * 4;

    // a_st[i] holds the A chunk with (chunk & 1) == i
    float4 a_st[2];
    float4 w_st = make_float4(0.f, 0.f, 0.f, 0.f);

    // ---- prologue: chunk0 -> smem stage 0; A chunks 1,2 -> regs; W chunk 1
    {
        float4 t = *reinterpret_cast<const float4*>(aptr);          // chunk 0
        As[0][aq * 4 + 0][arow] = t.x;
        As[0][aq * 4 + 1][arow] = t.y;
        As[0][aq * 4 + 2][arow] = t.z;
        As[0][aq * 4 + 3][arow] = t.w;
        if (wactive) {
            float4 tw = *reinterpret_cast<const float4*>(wptr);     // chunk 0
            Ws2[0][wq * 4 + 0][wn] = make_float2(tw.x, tw.x);
            Ws2[0][wq * 4 + 1][wn] = make_float2(tw.y, tw.y);
            Ws2[0][wq * 4 + 2][wn] = make_float2(tw.z, tw.z);
            Ws2[0][wq * 4 + 3][wn] = make_float2(tw.w, tw.w);
        }
        a_st[1] = *reinterpret_cast<const float4*>(aptr + 16);      // chunk 1
        a_st[0] = *reinterpret_cast<const float4*>(aptr + 32);      // chunk 2
        if (wactive) w_st = *reinterpret_cast<const float4*>(wptr + 16); // ch 1
    }
    __syncthreads();

    unsigned long long acc[4][10];
    #pragma unroll
    for (int i = 0; i < 4; ++i)
        #pragma unroll
        for (int c = 0; c < 10; ++c) acc[i][c] = 0ULL;

    for (int c = 0; c < NCHUNK; ++c) {
        const int nb = (c + 1) & 1;
        // STS chunk c+1 (held in a_st[nb] / w_st) into the other smem stage
        if (c + 1 < NCHUNK) {
            As[nb][aq * 4 + 0][arow] = a_st[nb].x;
            As[nb][aq * 4 + 1][arow] = a_st[nb].y;
            As[nb][aq * 4 + 2][arow] = a_st[nb].z;
            As[nb][aq * 4 + 3][arow] = a_st[nb].w;
            if (wactive) {
                Ws2[nb][wq * 4 + 0][wn] = make_float2(w_st.x, w_st.x);
                Ws2[nb][wq * 4 + 1][wn] = make_float2(w_st.y, w_st.y);
                Ws2[nb][wq * 4 + 2][wn] = make_float2(w_st.z, w_st.z);
                Ws2[nb][wq * 4 + 3][wn] = make_float2(w_st.w, w_st.w);
            }
        }
        // A: LDG chunk c+3 into the register slot just consumed (distance 3)
        if (c + 3 < NCHUNK)
            a_st[nb] = *reinterpret_cast<const float4*>(aptr + (c + 3) * 16);
        // W: LDG chunk c+2 (distance 2, L2-resident)
        if (wactive && c + 2 < NCHUNK)
            w_st = *reinterpret_cast<const float4*>(wptr + (c + 2) * 16);

        // compute chunk c from stage c&1
        const int s = c & 1;
        #pragma unroll
        for (int half = 0; half < 2; ++half) {
            const int k = phase + half * 8;     // ascending within chain
            ulonglong2 A0 = *reinterpret_cast<const ulonglong2*>(&As[s][k][wrow * 8]);
            ulonglong2 A1 = *reinterpret_cast<const ulonglong2*>(&As[s][k][wrow * 8 + 4]);
            // 5x LDS.128: duplicated-pair b operands {0,1},{2,3},{4,5},{6,7},{8,9}
            const float2* bp = &Ws2[s][k][wcol * 10];
            ulonglong2 B01 = *reinterpret_cast<const ulonglong2*>(bp + 0);
            ulonglong2 B23 = *reinterpret_cast<const ulonglong2*>(bp + 2);
            ulonglong2 B45 = *reinterpret_cast<const ulonglong2*>(bp + 4);
            ulonglong2 B67 = *reinterpret_cast<const ulonglong2*>(bp + 6);
            ulonglong2 B89 = *reinterpret_cast<const ulonglong2*>(bp + 8);
            unsigned long long b[10] = { B01.x, B01.y, B23.x, B23.y, B45.x,
                                         B45.y, B67.x, B67.y, B89.x, B89.y };
            #pragma unroll
            for (int cc = 0; cc < 10; ++cc) {
                fma2(acc[0][cc], A0.x, b[cc]);
                fma2(acc[1][cc], A0.y, b[cc]);
                fma2(acc[2][cc], A1.x, b[cc]);
                fma2(acc[3][cc], A1.y, b[cc]);
            }
        }
        __syncthreads();   // STS(c+1) visible; readers of stage s done
    }

    // Cross-phase combine: butterfly xor {4,1,2} == exact pairwise tree
    #pragma unroll
    for (int i = 0; i < 4; ++i) {
        #pragma unroll
        for (int cc = 0; cc < 10; ++cc) {
            unsigned long long v = acc[i][cc];
            v = add2(v, __shfl_xor_sync(0xFFFFFFFFu, v, 4));
            v = add2(v, __shfl_xor_sync(0xFFFFFFFFu, v, 1));
            v = add2(v, __shfl_xor_sync(0xFFFFFFFFu, v, 2));
            if (phase == 0) {
                const int n  = wcol * 10 + cc;
                const int m0 = mbase + wrow * 8 + i * 2;
                g_cur[(size_t)m0 * NN + n] =
                    __uint_as_float((unsigned int)(v & 0xFFFFFFFFu));
                g_cur[(size_t)(m0 + 1) * NN + n] =
                    __uint_as_float((unsigned int)(v >> 32));
            }
        }
    }
}

// ---------------------------------------------------------------------------
// Kernel 2 (EXACT R12 scan — measured 11.3us): LIF recurrence,
// 2 cells per thread (float2 I/O, ILP 2), ring prefetch depth 32.
//   mem_new = select(mem > 1, 0, unfused(0.95*mem + cur))   [== reference]
//   spk = (mem_new > 1)  [sign-exact vs (mem-1 > 0) via Sterbenz]
// ---------------------------------------------------------------------------
#define P2 (PLANE / 2)   // 5120 float2 per timestep

__global__ __launch_bounds__(32)
void snn_scan_kernel(float* __restrict__ out) {
    const int j = blockIdx.x * 32 + threadIdx.x;      // < 5120
    const float2* __restrict__ cp = reinterpret_cast<const float2*>(g_cur) + j;
    float2* __restrict__ sp = reinterpret_cast<float2*>(out) + j;
    float2* __restrict__ mp = reinterpret_cast<float2*>(out + OUT_HALF) + j;

    float2 buf[32];
    #pragma unroll
    for (int i = 0; i < 32; ++i) buf[i] = cp[(size_t)i * P2];

    float m0 = 0.0f, m1 = 0.0f;

    // 255 = 7*32 + 31: main t = 0..223, tail t = 224..254
    for (int t0 = 0; t0 < 224; t0 += 32) {
        #pragma unroll
        for (int u = 0; u < 32; ++u) {
            int t = t0 + u;
            float2 c = buf[u];
            int tn = t + 32; if (tn > TT - 1) tn = TT - 1;
            buf[u] = cp[(size_t)tn * P2];
            float n0 = __fadd_rn(__fmul_rn(0.95f, m0), c.x);
            float n1 = __fadd_rn(__fmul_rn(0.95f, m1), c.y);
            m0 = (m0 > 1.0f) ? 0.0f : n0;
            m1 = (m1 > 1.0f) ? 0.0f : n1;
            sp[(size_t)t * P2] = make_float2((m0 > 1.0f) ? 1.0f : 0.0f,
                                             (m1 > 1.0f) ? 1.0f : 0.0f);
            mp[(size_t)t * P2] = make_float2(m0, m1);
        }
    }
    #pragma unroll
    for (int u = 0; u < 31; ++u) {
        int t = 224 + u;
        float2 c = buf[u];
        float n0 = __fadd_rn(__fmul_rn(0.95f, m0), c.x);
        float n1 = __fadd_rn(__fmul_rn(0.95f, m1), c.y);
        m0 = (m0 > 1.0f) ? 0.0f : n0;
        m1 = (m1 > 1.0f) ? 0.0f : n1;
        sp[(size_t)t * P2] = make_float2((m0 > 1.0f) ? 1.0f : 0.0f,
                                         (m1 > 1.0f) ? 1.0f : 0.0f);
        mp[(size_t)t * P2] = make_float2(m0, m1);
    }
}

// ---------------------------------------------------------------------------
extern "C" void kernel_launch(void* const* d_in, const int* in_sizes, int n_in,
                              void* d_out, int out_size) {
    const float* x = (const float*)d_in[0];
    const float* W = (const float*)d_in[1];
    // Defensive: metadata order should be (x, W); swap if sizes say otherwise.
    if (n_in >= 2 && in_sizes[0] == NN * KK) {
        const float* t = x; x = W; W = t;
    }
    float* out = (float*)d_out;

    // Pattern [gemm, scan, nop]: ncu (-s 5 -c 1) captures the GEMM (proven R15).
    snn_gemm_kernel<<<MM / 64, 256>>>(x, W);    // 1020 blocks, 2 CTAs/SM
    snn_scan_kernel<<<P2 / 32, 32>>>(out);      // 160 blocks
    snn_nop_kernel<<<1, 32>>>();
}

// round 17
// speedup vs baseline: 1.3914x; 1.3914x over previous
#include <cuda_runtime.h>
#include <cstdint>
#include <cstddef>

// Problem constants
#define TT   255
#define BB   256
#define KK   784
#define NN   40
#define MM   (TT * BB)          // 65280
#define PLANE (BB * NN)         // 10240 elements per timestep
#define OUT_HALF (TT * PLANE)   // 2,611,200

// Scratch for cur = x @ W^T   (10.44 MB, static device global: allowed)
__device__ float g_cur[(size_t)MM * NN];

// packed f32x2 FMA: d = fma(a, b, d) per lane (IEEE rn, fused)
__device__ __forceinline__ void fma2(unsigned long long& d,
                                     unsigned long long a,
                                     unsigned long long b) {
    asm("fma.rn.f32x2 %0, %1, %2, %3;" : "=l"(d) : "l"(a), "l"(b), "l"(d));
}
// packed f32x2 add (rn)
__device__ __forceinline__ unsigned long long add2(unsigned long long a,
                                                   unsigned long long b) {
    unsigned long long d;
    asm("add.rn.f32x2 %0, %1, %2;" : "=l"(d) : "l"(a), "l"(b));
    return d;
}

// ---------------------------------------------------------------------------
// No-op kernel, launched LAST: with the harness's 2 pre-launches, ncu's
// -s 5 -c 1 capture lands on snn_gemm_kernel ((5-2) mod 3 == 0). Proven R15.
// ---------------------------------------------------------------------------
__global__ void snn_nop_kernel() {}

// ---------------------------------------------------------------------------
// Kernel 1: cur[m][n] = sum_k x[m][k] * W[n][k]
//
// Rounding scheme (bit-identical to all passing rounds):
//   8 chains, chain j = fused-FMA over k ≡ j (mod 8) ascending;
//   combine: ((c0+c4)+(c1+c5)) + ((c2+c6)+(c3+c7))
//   realized by phase-per-thread + butterfly shuffles xor {4,1,2}.
//
// R17: chunk loop UNROLLED BY 2 -> all smem stage indices compile-time
// (no runtime As[s] address math), and distance-3 A prefetch held in two
// NAMED registers aA/aB (fixes R16's dynamically-indexed a_st[2], which
// ptxas demoted to local memory -> the 255us regression).
//   iter c   (even): STS aA(chunk c+1)->stage1; aA=LDG(c+3); compute stage0
//   iter c+1 (odd) : STS aB(chunk c+2)->stage0; aB=LDG(c+4); compute stage1
// W: single reg, distance 2 (L2-resident). 49 chunks = 24 pairs + tail(48).
//
// 256 threads = 8 phases x 32 workers (8 row-groups x TM=8, 4 col-groups x
// TN=10). BM=64, BN=40, BK=16, grid = 1020, 2 CTAs/SM.
// ---------------------------------------------------------------------------
#define NCHUNK (KK / 16)    // 49

__global__ __launch_bounds__(256, 2)
void snn_gemm_kernel(const float* __restrict__ x, const float* __restrict__ W) {
    __shared__ float  As[2][16][68];
    __shared__ float2 Ws2[2][16][42];

    const int tid   = threadIdx.x;
    const int phase = tid & 7;          // chain index 0..7
    const int ww    = tid >> 3;         // worker 0..31
    const int wrow  = ww & 7;           // 8 row groups * TM=8 -> BM=64
    const int wcol  = ww >> 3;          // 4 col groups * TN=10 -> BN=40
    const int mbase = blockIdx.x * 64;

    // Staging-load geometry
    const int arow = tid >> 2;          // 0..63
    const int aq   = tid & 3;           // 0..3 (float4 within 16-k chunk)
    const float* __restrict__ aptr = x + (size_t)(mbase + arow) * KK + aq * 4;
    const int  wn      = tid >> 2;      // n index for W staging
    const int  wq      = tid & 3;
    const bool wactive = (tid < 160);   // 40 n * 4 quads
    const float* __restrict__ wptr = W + (size_t)wn * KK + wq * 4;

    // Named staging registers (never array-indexed):
    float4 aA, aB;                      // A chunks, distance-3 rotation
    float4 wv = make_float4(0.f, 0.f, 0.f, 0.f);  // W chunk, distance 2

    // ---- prologue: chunk0 -> smem stage0; aA=chunk1, aB=chunk2, wv=Wchunk1
    {
        float4 t = *reinterpret_cast<const float4*>(aptr);          // chunk 0
        As[0][aq * 4 + 0][arow] = t.x;
        As[0][aq * 4 + 1][arow] = t.y;
        As[0][aq * 4 + 2][arow] = t.z;
        As[0][aq * 4 + 3][arow] = t.w;
        if (wactive) {
            float4 tw = *reinterpret_cast<const float4*>(wptr);     // chunk 0
            Ws2[0][wq * 4 + 0][wn] = make_float2(tw.x, tw.x);
            Ws2[0][wq * 4 + 1][wn] = make_float2(tw.y, tw.y);
            Ws2[0][wq * 4 + 2][wn] = make_float2(tw.z, tw.z);
            Ws2[0][wq * 4 + 3][wn] = make_float2(tw.w, tw.w);
        }
        aA = *reinterpret_cast<const float4*>(aptr + 16);           // chunk 1
        aB = *reinterpret_cast<const float4*>(aptr + 32);           // chunk 2
        if (wactive) wv = *reinterpret_cast<const float4*>(wptr + 16); // ch 1
    }
    __syncthreads();

    unsigned long long acc[4][10];
    #pragma unroll
    for (int i = 0; i < 4; ++i)
        #pragma unroll
        for (int c = 0; c < 10; ++c) acc[i][c] = 0ULL;

    // Compute macro for stage S (compile-time): chunk's 2 k per phase.
    #define SNN_COMPUTE_STAGE(S)                                               \
    {                                                                          \
        _Pragma("unroll")                                                      \
        for (int half = 0; half < 2; ++half) {                                 \
            const int k = phase + half * 8;                                    \
            ulonglong2 A0 = *reinterpret_cast<const ulonglong2*>(              \
                &As[S][k][wrow * 8]);                                          \
            ulonglong2 A1 = *reinterpret_cast<const ulonglong2*>(              \
                &As[S][k][wrow * 8 + 4]);                                      \
            const float2* bp = &Ws2[S][k][wcol * 10];                          \
            ulonglong2 B01 = *reinterpret_cast<const ulonglong2*>(bp + 0);     \
            ulonglong2 B23 = *reinterpret_cast<const ulonglong2*>(bp + 2);     \
            ulonglong2 B45 = *reinterpret_cast<const ulonglong2*>(bp + 4);     \
            ulonglong2 B67 = *reinterpret_cast<const ulonglong2*>(bp + 6);     \
            ulonglong2 B89 = *reinterpret_cast<const ulonglong2*>(bp + 8);     \
            unsigned long long b[10] = { B01.x, B01.y, B23.x, B23.y, B45.x,    \
                                         B45.y, B67.x, B67.y, B89.x, B89.y };  \
            _Pragma("unroll")                                                  \
            for (int cc = 0; cc < 10; ++cc) {                                  \
                fma2(acc[0][cc], A0.x, b[cc]);                                 \
                fma2(acc[1][cc], A0.y, b[cc]);                                 \
                fma2(acc[2][cc], A1.x, b[cc]);                                 \
                fma2(acc[3][cc], A1.y, b[cc]);                                 \
            }                                                                  \
        }                                                                      \
    }

    #define SNN_STS_A(S, v)                                                    \
        As[S][aq * 4 + 0][arow] = (v).x;                                       \
        As[S][aq * 4 + 1][arow] = (v).y;                                       \
        As[S][aq * 4 + 2][arow] = (v).z;                                       \
        As[S][aq * 4 + 3][arow] = (v).w;

    #define SNN_STS_W(S)                                                       \
        if (wactive) {                                                         \
            Ws2[S][wq * 4 + 0][wn] = make_float2(wv.x, wv.x);                  \
            Ws2[S][wq * 4 + 1][wn] = make_float2(wv.y, wv.y);                  \
            Ws2[S][wq * 4 + 2][wn] = make_float2(wv.z, wv.z);                  \
            Ws2[S][wq * 4 + 3][wn] = make_float2(wv.w, wv.w);                  \
        }

    // Main: 24 pairs covering chunks 0..47
    for (int c = 0; c < NCHUNK - 1; c += 2) {
        // ---- iter c (even): compute stage 0
        SNN_STS_A(1, aA);                       // chunk c+1 -> stage 1
        SNN_STS_W(1);                           // W chunk c+1 -> stage 1
        if (wactive) wv = *reinterpret_cast<const float4*>(wptr + (c + 2) * 16);
        if (c + 3 < NCHUNK)
            aA = *reinterpret_cast<const float4*>(aptr + (c + 3) * 16);
        SNN_COMPUTE_STAGE(0)
        __syncthreads();

        // ---- iter c+1 (odd): compute stage 1
        SNN_STS_A(0, aB);                       // chunk c+2 -> stage 0
        SNN_STS_W(0);                           // W chunk c+2 -> stage 0
        if (wactive && c + 3 < NCHUNK)
            wv = *reinterpret_cast<const float4*>(wptr + (c + 3) * 16);
        if (c + 4 < NCHUNK)
            aB = *reinterpret_cast<const float4*>(aptr + (c + 4) * 16);
        SNN_COMPUTE_STAGE(1)
        __syncthreads();
    }
    // ---- tail: chunk 48 (stage 0, already stored at iter 47)
    SNN_COMPUTE_STAGE(0)

    #undef SNN_COMPUTE_STAGE
    #undef SNN_STS_A
    #undef SNN_STS_W

    // Cross-phase combine: butterfly xor {4,1,2} == exact pairwise tree
    #pragma unroll
    for (int i = 0; i < 4; ++i) {
        #pragma unroll
        for (int cc = 0; cc < 10; ++cc) {
            unsigned long long v = acc[i][cc];
            v = add2(v, __shfl_xor_sync(0xFFFFFFFFu, v, 4));
            v = add2(v, __shfl_xor_sync(0xFFFFFFFFu, v, 1));
            v = add2(v, __shfl_xor_sync(0xFFFFFFFFu, v, 2));
            if (phase == 0) {
                const int n  = wcol * 10 + cc;
                const int m0 = mbase + wrow * 8 + i * 2;
                g_cur[(size_t)m0 * NN + n] =
                    __uint_as_float((unsigned int)(v & 0xFFFFFFFFu));
                g_cur[(size_t)(m0 + 1) * NN + n] =
                    __uint_as_float((unsigned int)(v >> 32));
            }
        }
    }
}

// ---------------------------------------------------------------------------
// Kernel 2 (EXACT R12 scan — measured 11.3us): LIF recurrence,
// 2 cells per thread (float2 I/O, ILP 2), ring prefetch depth 32.
//   mem_new = select(mem > 1, 0, unfused(0.95*mem + cur))   [== reference]
//   spk = (mem_new > 1)  [sign-exact vs (mem-1 > 0) via Sterbenz]
// ---------------------------------------------------------------------------
#define P2 (PLANE / 2)   // 5120 float2 per timestep

__global__ __launch_bounds__(32)
void snn_scan_kernel(float* __restrict__ out) {
    const int j = blockIdx.x * 32 + threadIdx.x;      // < 5120
    const float2* __restrict__ cp = reinterpret_cast<const float2*>(g_cur) + j;
    float2* __restrict__ sp = reinterpret_cast<float2*>(out) + j;
    float2* __restrict__ mp = reinterpret_cast<float2*>(out + OUT_HALF) + j;

    float2 buf[32];
    #pragma unroll
    for (int i = 0; i < 32; ++i) buf[i] = cp[(size_t)i * P2];

    float m0 = 0.0f, m1 = 0.0f;

    // 255 = 7*32 + 31: main t = 0..223, tail t = 224..254
    for (int t0 = 0; t0 < 224; t0 += 32) {
        #pragma unroll
        for (int u = 0; u < 32; ++u) {
            int t = t0 + u;
            float2 c = buf[u];
            int tn = t + 32; if (tn > TT - 1) tn = TT - 1;
            buf[u] = cp[(size_t)tn * P2];
            float n0 = __fadd_rn(__fmul_rn(0.95f, m0), c.x);
            float n1 = __fadd_rn(__fmul_rn(0.95f, m1), c.y);
            m0 = (m0 > 1.0f) ? 0.0f : n0;
            m1 = (m1 > 1.0f) ? 0.0f : n1;
            sp[(size_t)t * P2] = make_float2((m0 > 1.0f) ? 1.0f : 0.0f,
                                             (m1 > 1.0f) ? 1.0f : 0.0f);
            mp[(size_t)t * P2] = make_float2(m0, m1);
        }
    }
    #pragma unroll
    for (int u = 0; u < 31; ++u) {
        int t = 224 + u;
        float2 c = buf[u];
        float n0 = __fadd_rn(__fmul_rn(0.95f, m0), c.x);
        float n1 = __fadd_rn(__fmul_rn(0.95f, m1), c.y);
        m0 = (m0 > 1.0f) ? 0.0f : n0;
        m1 = (m1 > 1.0f) ? 0.0f : n1;
        sp[(size_t)t * P2] = make_float2((m0 > 1.0f) ? 1.0f : 0.0f,
                                         (m1 > 1.0f) ? 1.0f : 0.0f);
        mp[(size_t)t * P2] = make_float2(m0, m1);
    }
}

// ---------------------------------------------------------------------------
extern "C" void kernel_launch(void* const* d_in, const int* in_sizes, int n_in,
                              void* d_out, int out_size) {
    const float* x = (const float*)d_in[0];
    const float* W = (const float*)d_in[1];
    // Defensive: metadata order should be (x, W); swap if sizes say otherwise.
    if (n_in >= 2 && in_sizes[0] == NN * KK) {
        const float* t = x; x = W; W = t;
    }
    float* out = (float*)d_out;

    // Pattern [gemm, scan, nop]: ncu (-s 5 -c 1) captures the GEMM (proven R15).
    snn_gemm_kernel<<<MM / 64, 256>>>(x, W);    // 1020 blocks, 2 CTAs/SM
    snn_scan_kernel<<<P2 / 32, 32>>>(out);      // 160 blocks
    snn_nop_kernel<<<1, 32>>>();
}